// round 6
// baseline (speedup 1.0000x reference)
#include <cuda_runtime.h>
#include <cstdint>

// T=4 tables, E=1,000,000 rows/table, D=128 dims, B=8192 bags, L=32 bag length
// indices: [T, B, L] (int32 OR int64 — detected inline per block)
// weights: fp32 [T, E, D]; output: fp32 [B, T*D]
// out[b, t*D + d] = sum_l weights[t, indices[t,b,l], d]
//
// Perf model (measured R2-R5): all variants pin at ~6.15 TB/s HBM — the B300
// path-independent LTS cap (~6300 B/cyc; lts__throughput reads ~49% of nominal
// = the documented empirical ceiling). Total L2 traffic 536MB -> ~80us floor.
// This version only tunes tail/overhead: 128-thread CTAs for finer SM load
// balancing, no inter-phase barriers (sequential t-loop keeps rough phase
// alignment for L2 capture of the ~12% repeated rows).

#define T_TABLES 4
#define E_ROWS   1000000
#define D_DIM    128
#define B_BATCH  8192
#define L_BAG    32

// One warp per bag b, looping over the 4 tables. 8192 warps = 2048 blocks x 4
// warps ~= one wave on 148 SMs (13-14 blocks/SM -> <4% quantization imbalance).
//
// Index dtype detected inline: warp 0 reads idx[0..31] as an int64 view. True
// int64 data (row ids < 1M) passes the range check on all lanes; int32 data
// viewed as int64 has random row-ids in the hi-words, so P(all 32 pass) ~ 0.
__global__ __launch_bounds__(128) void embbag_kernel(
    const void*  __restrict__ indices_raw,   // [T*B*L] int32 or int64
    const float* __restrict__ weights,       // [T*E*D]
    float*       __restrict__ out)           // [B*T*D]
{
    __shared__ int s_is64;

    const int lane = threadIdx.x & 31;
    const int b    = blockIdx.x * 4 + (threadIdx.x >> 5);   // 0..8191, exact

    if (threadIdx.x < 32) {
        const long long v = ((const long long*)indices_raw)[threadIdx.x];
        const unsigned bad = __ballot_sync(0xffffffffu, v < 0 || v >= E_ROWS);
        if (threadIdx.x == 0) s_is64 = (bad == 0u) ? 1 : 0;
    }
    __syncthreads();
    const int is64 = s_is64;

    const float4* __restrict__ wf4 = reinterpret_cast<const float4*>(weights);
    float4* __restrict__ of4 =
        reinterpret_cast<float4*>(out) + (size_t)b * (T_TABLES * D_DIM / 4);

    #pragma unroll 1
    for (int t = 0; t < T_TABLES; ++t) {
        // Each lane loads one of the 32 bag indices (coalesced, streaming).
        const size_t idx_off = ((size_t)t * B_BATCH + b) * L_BAG + lane;
        long long my_idx;
        if (is64) {
            my_idx = __ldcs(((const long long*)indices_raw) + idx_off);
        } else {
            my_idx = (long long)__ldcs(((const int*)indices_raw) + idx_off);
        }

        const float4* __restrict__ wbase = wf4 + (size_t)t * E_ROWS * (D_DIM / 4);

        float4 acc = make_float4(0.f, 0.f, 0.f, 0.f);
        #pragma unroll
        for (int l = 0; l < L_BAG; ++l) {
            const long long row = __shfl_sync(0xffffffffu, my_idx, l);
            const float4 v = __ldg(wbase + (size_t)row * (D_DIM / 4) + lane);
            acc.x += v.x; acc.y += v.y; acc.z += v.z; acc.w += v.w;
        }

        // Streaming store: output is never re-read; don't pollute L2.
        __stcs(of4 + t * (D_DIM / 4) + lane, acc);
    }
}

extern "C" void kernel_launch(void* const* d_in, const int* in_sizes, int n_in,
                              void* d_out, int out_size)
{
    // Identify inputs by element count (robust to metadata ordering):
    // indices: T*B*L = 1,048,576 ; weights: T*E*D = 512,000,000
    const void*  indices = d_in[0];
    const float* weights = (const float*)d_in[1];
    if (n_in >= 2) {
        long long s0 = in_sizes[0], s1 = in_sizes[1];
        if (s0 > s1) {
            weights = (const float*)d_in[0];
            indices = d_in[1];
        }
    }
    float* out = (float*)d_out;

    const int blocks  = B_BATCH / 4;   // 2048 blocks x 4 warps = 8192 warps
    const int threads = 128;
    embbag_kernel<<<blocks, threads>>>(indices, weights, out);
}

// round 7
// speedup vs baseline: 1.0299x; 1.0299x over previous
#include <cuda_runtime.h>
#include <cstdint>

// T=4 tables, E=1,000,000 rows/table, D=128 dims, B=8192 bags, L=32 bag length
// indices: [T, B, L] (int32 OR int64 — detected inline per warp)
// weights: fp32 [T, E, D]; output: fp32 [B, T*D]
// out[b, t*D + d] = sum_l weights[t, indices[t,b,l], d]
//
// Perf model (R2-R6 measured): DRAM traffic is at the dedup minimum (~490MB);
// throughput pins at ~6.2 TB/s (B300 LTS path-independent cap). Floor ~79us.
// Config matters only via phase alignment + occupancy:
//   - 256-thread blocks + per-phase __syncthreads(): best (R5, 80.8us kernel)
//   - no barriers / 128-thread blocks: worse DRAM eff + occupancy (R6, 82.9us)
// This is R5 with warp-local dtype detection (no entry barrier / smem).

#define T_TABLES 4
#define E_ROWS   1000000
#define D_DIM    128
#define B_BATCH  8192
#define L_BAG    32

// One warp per bag b, looping over the 4 tables in phase order. 8192 warps =
// 1024 blocks x 8 warps = one wave on 148 SMs; all resident warps stream the
// SAME table's ~131MB footprint concurrently so L2 captures the ~12% repeats.
//
// Index dtype detected per warp: every warp reads idx[0..31] as an int64 view
// (same 256B line chip-wide -> L2 hit). True int64 data (row ids < 1M) passes
// the range check on all lanes; int32 data viewed as int64 has random row-ids
// in the hi-words, so P(all 32 pass) ~= (1e-6)^32 ~ 0.
__global__ __launch_bounds__(256) void embbag_kernel(
    const void*  __restrict__ indices_raw,   // [T*B*L] int32 or int64
    const float* __restrict__ weights,       // [T*E*D]
    float*       __restrict__ out)           // [B*T*D]
{
    const int lane = threadIdx.x & 31;
    const int b    = blockIdx.x * 8 + (threadIdx.x >> 5);   // 0..8191, exact

    // Warp-local dtype probe (no barrier, no smem).
    const long long pv = __ldg(((const long long*)indices_raw) + lane);
    const unsigned bad = __ballot_sync(0xffffffffu, pv < 0 || pv >= E_ROWS);
    const int is64 = (bad == 0u) ? 1 : 0;

    const float4* __restrict__ wf4 = reinterpret_cast<const float4*>(weights);
    float4* __restrict__ of4 =
        reinterpret_cast<float4*>(out) + (size_t)b * (T_TABLES * D_DIM / 4);

    #pragma unroll 1
    for (int t = 0; t < T_TABLES; ++t) {
        // Each lane loads one of the 32 bag indices (coalesced, streaming).
        const size_t idx_off = ((size_t)t * B_BATCH + b) * L_BAG + lane;
        long long my_idx;
        if (is64) {
            my_idx = __ldcs(((const long long*)indices_raw) + idx_off);
        } else {
            my_idx = (long long)__ldcs(((const int*)indices_raw) + idx_off);
        }

        const float4* __restrict__ wbase = wf4 + (size_t)t * E_ROWS * (D_DIM / 4);

        float4 acc = make_float4(0.f, 0.f, 0.f, 0.f);
        #pragma unroll
        for (int l = 0; l < L_BAG; ++l) {
            const long long row = __shfl_sync(0xffffffffu, my_idx, l);
            const float4 v = __ldg(wbase + (size_t)row * (D_DIM / 4) + lane);
            acc.x += v.x; acc.y += v.y; acc.z += v.z; acc.w += v.w;
        }

        // Streaming store: output is never re-read; don't pollute L2.
        __stcs(of4 + t * (D_DIM / 4) + lane, acc);

        // Keep the block phase-aligned on the same table for L2 locality.
        __syncthreads();
    }
}

extern "C" void kernel_launch(void* const* d_in, const int* in_sizes, int n_in,
                              void* d_out, int out_size)
{
    // Identify inputs by element count (robust to metadata ordering):
    // indices: T*B*L = 1,048,576 ; weights: T*E*D = 512,000,000
    const void*  indices = d_in[0];
    const float* weights = (const float*)d_in[1];
    if (n_in >= 2) {
        long long s0 = in_sizes[0], s1 = in_sizes[1];
        if (s0 > s1) {
            weights = (const float*)d_in[0];
            indices = d_in[1];
        }
    }
    float* out = (float*)d_out;

    const int blocks  = B_BATCH / 8;   // 1024 blocks x 8 warps = 8192 warps, 1 wave
    const int threads = 256;
    embbag_kernel<<<blocks, threads>>>(indices, weights, out);
}

// round 8
// speedup vs baseline: 1.0541x; 1.0235x over previous
#include <cuda_runtime.h>
#include <cstdint>

// T=4 tables, E=1,000,000 rows/table, D=128 dims, B=8192 bags, L=32 bag length
// indices: [T, B, L] (int32 OR int64 — detected inline per warp)
// weights: fp32 [T, E, D]; output: fp32 [B, T*D]
// out[b, t*D + d] = sum_l weights[t, indices[t,b,l], d]
//
// Perf model (R2-R7 measured): DRAM traffic is at the dedup minimum (~490MB);
// throughput pins at ~6.2 TB/s (B300 LTS path-independent cap). Floor ~79us.
// Best config (R7): 256-thread blocks, warp-per-bag, phase-locked t-loop with
// __syncthreads(), warp-local dtype probe. This round adds index-load
// software pipelining: table t+1's bag indices are fetched before table t's
// gather loop, hiding the ~600-cycle post-barrier index-load stall behind the
// 32 row gathers.

#define T_TABLES 4
#define E_ROWS   1000000
#define D_DIM    128
#define B_BATCH  8192
#define L_BAG    32

// Index dtype detected per warp: every warp reads idx[0..31] as an int64 view
// (same 256B line chip-wide -> L2 hit). True int64 data (row ids < 1M) passes
// the range check on all lanes; int32 data viewed as int64 has random row-ids
// in the hi-words, so P(all 32 pass) ~= (1e-6)^32 ~ 0.
__global__ __launch_bounds__(256) void embbag_kernel(
    const void*  __restrict__ indices_raw,   // [T*B*L] int32 or int64
    const float* __restrict__ weights,       // [T*E*D]
    float*       __restrict__ out)           // [B*T*D]
{
    const int lane = threadIdx.x & 31;
    const int b    = blockIdx.x * 8 + (threadIdx.x >> 5);   // 0..8191, exact

    // Warp-local dtype probe (no barrier, no smem).
    const long long pv = __ldg(((const long long*)indices_raw) + lane);
    const unsigned bad = __ballot_sync(0xffffffffu, pv < 0 || pv >= E_ROWS);
    const int is64 = (bad == 0u) ? 1 : 0;

    const float4* __restrict__ wf4 = reinterpret_cast<const float4*>(weights);
    float4* __restrict__ of4 =
        reinterpret_cast<float4*>(out) + (size_t)b * (T_TABLES * D_DIM / 4);

    // Coalesced streaming load of this warp's 32 bag indices for table t.
    auto load_bag = [&](int t) -> long long {
        const size_t off = ((size_t)t * B_BATCH + b) * L_BAG + lane;
        return is64 ? __ldcs(((const long long*)indices_raw) + off)
                    : (long long)__ldcs(((const int*)indices_raw) + off);
    };

    long long my_idx = load_bag(0);

    #pragma unroll 1
    for (int t = 0; t < T_TABLES; ++t) {
        // Prefetch next table's indices; latency hides behind the 32 gathers.
        // Clamp at t=3 to a valid region (value unused).
        const long long next_idx = load_bag(t < T_TABLES - 1 ? t + 1 : t);

        const float4* __restrict__ wbase = wf4 + (size_t)t * E_ROWS * (D_DIM / 4);

        float4 acc = make_float4(0.f, 0.f, 0.f, 0.f);
        #pragma unroll
        for (int l = 0; l < L_BAG; ++l) {
            const long long row = __shfl_sync(0xffffffffu, my_idx, l);
            const float4 v = __ldg(wbase + (size_t)row * (D_DIM / 4) + lane);
            acc.x += v.x; acc.y += v.y; acc.z += v.z; acc.w += v.w;
        }

        // Streaming store: output is never re-read; don't pollute L2.
        __stcs(of4 + t * (D_DIM / 4) + lane, acc);

        // Keep the block phase-aligned on the same table for L2 locality.
        __syncthreads();

        my_idx = next_idx;
    }
}

extern "C" void kernel_launch(void* const* d_in, const int* in_sizes, int n_in,
                              void* d_out, int out_size)
{
    // Identify inputs by element count (robust to metadata ordering):
    // indices: T*B*L = 1,048,576 ; weights: T*E*D = 512,000,000
    const void*  indices = d_in[0];
    const float* weights = (const float*)d_in[1];
    if (n_in >= 2) {
        long long s0 = in_sizes[0], s1 = in_sizes[1];
        if (s0 > s1) {
            weights = (const float*)d_in[0];
            indices = d_in[1];
        }
    }
    float* out = (float*)d_out;

    const int blocks  = B_BATCH / 8;   // 1024 blocks x 8 warps = 8192 warps, 1 wave
    const int threads = 256;
    embbag_kernel<<<blocks, threads>>>(indices, weights, out);
}